// round 16
// baseline (speedup 1.0000x reference)
#include <cuda_runtime.h>
#include <cuda_fp16.h>
#include <math.h>
#include <stdint.h>

// ---------------- problem constants ----------------
#define BATCH   4
#define SEQ     1500
#define CDIM    1024
#define NHEAD   16
#define HDIM    64
#define FDIM    4096
#define ADIM    256
#define MROWS   (BATCH * SEQ)          // 6000
#define QKSCALE 0.35355339059327379f   // 64^-0.25
#define LOG2E   1.4426950408889634f

// ---------------- scratch ----------------
__device__ float g_x1[MROWS * CDIM];
__device__ float g_p [2 * MROWS * CDIM];   // split-K partials for W2

__device__ __half g_q[MROWS * CDIM];
__device__ __half g_k[MROWS * CDIM];
__device__ __half g_v[MROWS * CDIM];

__device__ __half g_H[MROWS * CDIM];
__device__ __half g_F[MROWS * FDIM];
__device__ __half g_D[MROWS * ADIM];

#define CC      (CDIM * CDIM)
#define W1SZ    (FDIM * CDIM)
#define ASZ     (ADIM * CDIM)
#define OFF_WQ  0
#define OFF_WK  (CC)
#define OFF_WV  (2 * CC)
#define OFF_WO  (3 * CC)
#define OFF_W1  (4 * CC)
#define OFF_W2  (4 * CC + W1SZ)
#define OFF_WDS (4 * CC + 2 * W1SZ)
#define OFF_WUS (4 * CC + 2 * W1SZ + ASZ)
#define WTOT    (4 * CC + 2 * W1SZ + 2 * ASZ)
__device__ __half g_W[WTOT];

// ---------------- helpers ----------------
__device__ __forceinline__ float gelu_exact(float v) {
    return 0.5f * v * (1.0f + erff(v * 0.70710678118654752f));
}
__device__ __forceinline__ uint32_t smem_u32(const void* p) {
    uint32_t a;
    asm("{ .reg .u64 t; cvta.to.shared.u64 t, %1; cvt.u32.u64 %0, t; }" : "=r"(a) : "l"(p));
    return a;
}
__device__ __forceinline__ void cp_async16(uint32_t dst, const void* src) {
    asm volatile("cp.async.cg.shared.global [%0], [%1], 16;" :: "r"(dst), "l"(src));
}
__device__ __forceinline__ void ldsm_x4(uint32_t& r0, uint32_t& r1, uint32_t& r2,
                                        uint32_t& r3, uint32_t addr) {
    asm volatile("ldmatrix.sync.aligned.m8n8.x4.shared.b16 {%0,%1,%2,%3}, [%4];"
        : "=r"(r0), "=r"(r1), "=r"(r2), "=r"(r3) : "r"(addr));
}
__device__ __forceinline__ void ldsm_x4t(uint32_t& r0, uint32_t& r1, uint32_t& r2,
                                         uint32_t& r3, uint32_t addr) {
    asm volatile("ldmatrix.sync.aligned.m8n8.x4.trans.shared.b16 {%0,%1,%2,%3}, [%4];"
        : "=r"(r0), "=r"(r1), "=r"(r2), "=r"(r3) : "r"(addr));
}
__device__ __forceinline__ void mma_f16(float* c, const uint32_t* a, const uint32_t* b) {
    asm volatile("mma.sync.aligned.m16n8k16.row.col.f32.f16.f16.f32 "
        "{%0,%1,%2,%3}, {%4,%5,%6,%7}, {%8,%9}, {%0,%1,%2,%3};"
        : "+f"(c[0]), "+f"(c[1]), "+f"(c[2]), "+f"(c[3])
        : "r"(a[0]), "r"(a[1]), "r"(a[2]), "r"(a[3]), "r"(b[0]), "r"(b[1]));
}
__device__ __forceinline__ uint32_t packh2(float a, float b) {
    __half2 h = __floats2half2_rn(a, b);
    return *reinterpret_cast<uint32_t*>(&h);
}
__device__ __forceinline__ uint32_t ex2_h2(uint32_t s) {
    uint32_t p;
    asm("ex2.approx.f16x2 %0, %1;" : "=r"(p) : "r"(s));
    return p;
}
#define SWZOFF(row, ch) ((uint32_t)((((row) * 8) + ((ch) ^ ((row) & 7))) * 16))

// ---------------- fused weight conversion ----------------
struct CvtArgs {
    const float* src[8];
    int off4[9];
};
__global__ __launch_bounds__(256) void cvt_all_kernel(CvtArgs a, __half* __restrict__ W) {
    const int i = blockIdx.x * 256 + threadIdx.x;
    if (i >= a.off4[8]) return;
    int seg = 0;
    #pragma unroll
    for (int s = 1; s < 8; s++) if (i >= a.off4[s]) seg = s;
    const int li = i - a.off4[seg];
    float4 v = reinterpret_cast<const float4*>(a.src[seg])[li];
    __half2* dp = reinterpret_cast<__half2*>(W + (size_t)i * 4);
    dp[0] = __floats2half2_rn(v.x, v.y);
    dp[1] = __floats2half2_rn(v.z, v.w);
}

// ---------------- LayerNorm: 2 rows per block, 128 threads/row ----------------
__global__ __launch_bounds__(256) void ln_h_kernel(const float* __restrict__ x,
                                                   const float* __restrict__ w,
                                                   const float* __restrict__ b,
                                                   __half* __restrict__ oh) {
    __shared__ float red[2][2][4];   // [rowhalf][sum/sumsq][warp]
    const int rh  = threadIdx.x >> 7;          // 0 or 1: row within block
    const int row = blockIdx.x * 2 + rh;
    const int tid = threadIdx.x & 127;         // 0..127 within row
    const int lane = threadIdx.x & 31, wid = (threadIdx.x >> 5) & 3;

    const float* xp = x + (size_t)row * CDIM;
    float4 v0 = reinterpret_cast<const float4*>(xp)[tid];
    float4 v1 = reinterpret_cast<const float4*>(xp)[tid + 128];
    float s  = v0.x + v0.y + v0.z + v0.w + v1.x + v1.y + v1.z + v1.w;
    float ss = v0.x*v0.x + v0.y*v0.y + v0.z*v0.z + v0.w*v0.w
             + v1.x*v1.x + v1.y*v1.y + v1.z*v1.z + v1.w*v1.w;
    #pragma unroll
    for (int o = 16; o; o >>= 1) {
        s  += __shfl_xor_sync(0xffffffffu, s,  o);
        ss += __shfl_xor_sync(0xffffffffu, ss, o);
    }
    if (lane == 0) { red[rh][0][wid] = s; red[rh][1][wid] = ss; }
    __syncthreads();
    float fs = 0.f, fss = 0.f;
    #pragma unroll
    for (int i = 0; i < 4; i++) { fs += red[rh][0][i]; fss += red[rh][1][i]; }
    const float mu  = fs * (1.0f / CDIM);
    const float var = fss * (1.0f / CDIM) - mu * mu;
    const float r   = rsqrtf(var + 1e-5f);

    float4 w0 = reinterpret_cast<const float4*>(w)[tid];
    float4 w1 = reinterpret_cast<const float4*>(w)[tid + 128];
    float4 b0 = reinterpret_cast<const float4*>(b)[tid];
    float4 b1 = reinterpret_cast<const float4*>(b)[tid + 128];
    __half2* hp = reinterpret_cast<__half2*>(oh + (size_t)row * CDIM);
    hp[tid * 2 + 0] = __floats2half2_rn((v0.x - mu) * r * w0.x + b0.x,
                                        (v0.y - mu) * r * w0.y + b0.y);
    hp[tid * 2 + 1] = __floats2half2_rn((v0.z - mu) * r * w0.z + b0.z,
                                        (v0.w - mu) * r * w0.w + b0.w);
    hp[256 + tid * 2 + 0] = __floats2half2_rn((v1.x - mu) * r * w1.x + b1.x,
                                              (v1.y - mu) * r * w1.y + b1.y);
    hp[256 + tid * 2 + 1] = __floats2half2_rn((v1.z - mu) * r * w1.z + b1.z,
                                              (v1.w - mu) * r * w1.w + b1.w);
}

// ---------------- split-K reduction: out = p0 + p1 + b2 + x1; H = half(out) ----------------
__global__ __launch_bounds__(256) void red_kernel(const float* __restrict__ p,
                                                  const float* __restrict__ x1,
                                                  const float* __restrict__ b2,
                                                  float* __restrict__ out,
                                                  __half* __restrict__ H) {
    const int i = blockIdx.x * 256 + threadIdx.x;      // float4 units
    if (i >= MROWS * CDIM / 4) return;
    float4 a = reinterpret_cast<const float4*>(p)[i];
    float4 b = reinterpret_cast<const float4*>(p)[i + MROWS * CDIM / 4];
    float4 r = reinterpret_cast<const float4*>(x1)[i];
    float4 bb = reinterpret_cast<const float4*>(b2)[i & 255];
    float4 o;
    o.x = a.x + b.x + r.x + bb.x;
    o.y = a.y + b.y + r.y + bb.y;
    o.z = a.z + b.z + r.z + bb.z;
    o.w = a.w + b.w + r.w + bb.w;
    reinterpret_cast<float4*>(out)[i] = o;
    __half2* hp = reinterpret_cast<__half2*>(H + (size_t)i * 4);
    hp[0] = __floats2half2_rn(o.x, o.y);
    hp[1] = __floats2half2_rn(o.z, o.w);
}

// ---------------- fp16 tensor-core GEMM, multi-stage cp.async pipeline (R13 mainloop) ----------------
// MODE 0: v = acc+bias(+res) -> fp32 out (optional half copy to Oh)
// MODE 1: v = gelu(acc+bias) -> half out (Oh)
// MODE 3: fused QKV; MODE 4: split-K partial
#define GEMM_SMEM 98304

template<int MODE, bool HCOPY, int TM>
__global__ __launch_bounds__(256, 2) void gemm_mma(
        const __half* __restrict__ A, const __half* __restrict__ B,
        const float* __restrict__ bias, const float* __restrict__ bias2,
        const float* __restrict__ res,
        float* __restrict__ out, __half* __restrict__ Oh,
        __half* __restrict__ Kp, __half* __restrict__ Vp,
        int M, int N, int K, int ld, float scale) {
    constexpr int WM = TM / 32;
    constexpr int WN = 8 / WM;
    constexpr int WNC = 128 / WN;
    constexpr int NT = WNC / 8;
    constexpr int TILEA = TM * 128;
    constexpr int TILEB2 = 128 * 128;
    constexpr int STAGE = TILEA + TILEB2;
    constexpr int NST = (TM == 128) ? 3 : 4;
    constexpr int P = NST - 1;

    extern __shared__ char smem[];
    const uint32_t sbase = smem_u32(smem);
    const int tid  = threadIdx.x;
    const int warp = tid >> 5, lane = tid & 31;
    const int bm = blockIdx.y * TM, bn = blockIdx.x * 128;
    const int wm = warp % WM, wn = warp / WM;

    const bool lact = tid < TM + 128;
    const bool isA = tid < TM;
    const int lrow = isA ? tid : tid - TM;
    const __half* lsrc = isA ? A : B;
    const int gr = isA ? min(bm + lrow, M - 1) : (bn + lrow);
    const int koff = (MODE == 4) ? blockIdx.z * K : 0;
    const __half* src = lsrc + (size_t)gr * ld + koff;
    const uint32_t dbase0 = sbase + (isA ? 0 : TILEA);
    uint32_t doff[8];
    #pragma unroll
    for (int c = 0; c < 8; c++) doff[c] = SWZOFF(lrow, c);

    float acc[2][NT][4];
    #pragma unroll
    for (int a = 0; a < 2; a++)
        #pragma unroll
        for (int b = 0; b < NT; b++)
            #pragma unroll
            for (int c = 0; c < 4; c++) acc[a][b][c] = 0.f;

    const int nch = K / 64;

    #pragma unroll
    for (int p = 0; p < P; p++) {
        if (p < nch && lact) {
            const uint32_t db = dbase0 + p * STAGE;
            const int k0 = p * 64;
            #pragma unroll
            for (int c = 0; c < 8; c++) cp_async16(db + doff[c], src + k0 + c * 8);
        }
        asm volatile("cp.async.commit_group;");
    }

    const int arow = (lane & 15);
    const int acsel = lane >> 4;
    const int brow = (lane & 7) + ((lane >> 4) & 1) * 8;
    const int bcsel = (lane >> 3) & 1;

    int stc = 0;
    for (int kc = 0; kc < nch; kc++) {
        if constexpr (NST == 3) asm volatile("cp.async.wait_group 1;");
        else                    asm volatile("cp.async.wait_group 2;");
        __syncthreads();

        const uint32_t base = sbase + stc * STAGE;
        const uint32_t aB = base, bB = base + TILEA;

        // ---- peel ks=0 fragment loads before issuing next chunk's cp.async ----
        uint32_t af0[2][4], bf0[NT][2];
        #pragma unroll
        for (int mt = 0; mt < 2; mt++) {
            const int row = wm * 32 + mt * 16 + arow;
            const uint32_t off = SWZOFF(row, acsel);
            ldsm_x4(af0[mt][0], af0[mt][1], af0[mt][2], af0[mt][3], aB + off);
        }
        #pragma unroll
        for (int np = 0; np < NT / 2; np++) {
            const int row = wn * WNC + np * 16 + brow;
            const uint32_t off = SWZOFF(row, bcsel);
            uint32_t r0, r1, r2, r3;
            ldsm_x4(r0, r1, r2, r3, bB + off);
            bf0[np*2][0] = r0; bf0[np*2][1] = r1; bf0[np*2+1][0] = r2; bf0[np*2+1][1] = r3;
        }

        // ---- issue next chunk load (overlaps ldmatrix latency) ----
        {
            const int cload = kc + P;
            if (cload < nch && lact) {
                const int sti = (stc == 0) ? (NST - 1) : (stc - 1);
                const uint32_t db = dbase0 + sti * STAGE;
                const int k0 = cload * 64;
                #pragma unroll
                for (int c = 0; c < 8; c++) cp_async16(db + doff[c], src + k0 + c * 8);
            }
            asm volatile("cp.async.commit_group;");
        }

        // ---- ks=0 mma ----
        #pragma unroll
        for (int mt = 0; mt < 2; mt++)
            #pragma unroll
            for (int nt = 0; nt < NT; nt++)
                mma_f16(acc[mt][nt], af0[mt], bf0[nt]);

        // ---- ks = 1..3 ----
        #pragma unroll
        for (int ks = 1; ks < 4; ks++) {
            uint32_t af[2][4], bf[NT][2];
            #pragma unroll
            for (int mt = 0; mt < 2; mt++) {
                const int row = wm * 32 + mt * 16 + arow;
                const uint32_t off = SWZOFF(row, ks * 2 + acsel);
                ldsm_x4(af[mt][0], af[mt][1], af[mt][2], af[mt][3], aB + off);
            }
            #pragma unroll
            for (int np = 0; np < NT / 2; np++) {
                const int row = wn * WNC + np * 16 + brow;
                const uint32_t off = SWZOFF(row, ks * 2 + bcsel);
                uint32_t r0, r1, r2, r3;
                ldsm_x4(r0, r1, r2, r3, bB + off);
                bf[np*2][0] = r0; bf[np*2][1] = r1; bf[np*2+1][0] = r2; bf[np*2+1][1] = r3;
            }
            #pragma unroll
            for (int mt = 0; mt < 2; mt++)
                #pragma unroll
                for (int nt = 0; nt < NT; nt++)
                    mma_f16(acc[mt][nt], af[mt], bf[nt]);
        }
        stc = (stc + 1 == NST) ? 0 : stc + 1;
    }

    // ---------------- epilogue ----------------
    __half* dst3 = Oh;
    const float* bb3 = bias;
    float sc3 = scale;
    if (MODE == 3) {
        const int seg = bn >> 10;
        dst3 = (seg == 0) ? Oh : ((seg == 1) ? Kp : Vp);
        bb3  = (seg == 0) ? bias : ((seg == 2) ? bias2 : nullptr);
        sc3  = (seg == 0) ? scale * LOG2E : ((seg == 1) ? scale : 1.0f);
    }
    float* out4 = out;
    if (MODE == 4) out4 = out + (size_t)blockIdx.z * M * N;

    const int g = lane >> 2, t = lane & 3;
    #pragma unroll
    for (int mt = 0; mt < 2; mt++) {
        #pragma unroll
        for (int half = 0; half < 2; half++) {
            const int m = bm + wm * 32 + mt * 16 + g + half * 8;
            if (m >= M) continue;
            int bI = 0, sI = 0;
            if (MODE == 3) { bI = m / SEQ; sI = m - bI * SEQ; }
            #pragma unroll
            for (int nt = 0; nt < NT; nt++) {
                const int n = bn + wn * WNC + nt * 8 + t * 2;
                float v0 = acc[mt][nt][half * 2 + 0];
                float v1 = acc[mt][nt][half * 2 + 1];
                if (MODE == 4) {
                    const size_t idx = (size_t)m * N + n;
                    *reinterpret_cast<float2*>(out4 + idx) = make_float2(v0, v1);
                } else if (MODE == 3) {
                    const int nn = n & 1023;
                    if (bb3) {
                        float2 b2 = *reinterpret_cast<const float2*>(bb3 + nn);
                        v0 += b2.x; v1 += b2.y;
                    }
                    v0 *= sc3; v1 *= sc3;
                    const int hd = nn >> 6, dd = nn & 63;
                    const size_t idx = (((size_t)bI * NHEAD + hd) * SEQ + sI) * HDIM + dd;
                    *reinterpret_cast<__half2*>(dst3 + idx) = __floats2half2_rn(v0, v1);
                } else {
                    if (bias) {
                        float2 b2 = *reinterpret_cast<const float2*>(bias + n);
                        v0 += b2.x; v1 += b2.y;
                    }
                    if (MODE == 1) {
                        v0 = gelu_exact(v0); v1 = gelu_exact(v1);
                        const size_t idx = (size_t)m * N + n;
                        *reinterpret_cast<__half2*>(Oh + idx) = __floats2half2_rn(v0, v1);
                    } else {
                        const size_t idx = (size_t)m * N + n;
                        if (res) {
                            float2 r2 = *reinterpret_cast<const float2*>(res + idx);
                            v0 += r2.x; v1 += r2.y;
                        }
                        *reinterpret_cast<float2*>(out + idx) = make_float2(v0, v1);
                        if (HCOPY)
                            *reinterpret_cast<__half2*>(Oh + idx) = __floats2half2_rn(v0, v1);
                    }
                }
            }
        }
    }
}

// ---------------- tensor-core flash attention (fp16, static-max softmax, f16x2 ex2) ----------------
// R13 configuration: 64-row KV tiles, 2-stage double buffer (measured optimum).
#define ATQ 128
#define ATK 64
#define QTILE_B (ATQ * 128)
#define KTILE_B (ATK * 128)
#define AT_ST0  (QTILE_B)
#define AT_STAGE (2 * KTILE_B)
#define ATT_SMEM (QTILE_B + 2 * AT_STAGE)   // 49152

__global__ __launch_bounds__(256, 2) void attn_mma(
        const __half* __restrict__ Q, const __half* __restrict__ Kp,
        const __half* __restrict__ V, __half* __restrict__ O) {
    extern __shared__ char smem[];
    const uint32_t sbase = smem_u32(smem);
    const int tid = threadIdx.x;
    const int warp = tid >> 5, lane = tid & 31;
    const int b = blockIdx.z, h = blockIdx.y;
    const int q0 = blockIdx.x * ATQ;
    const size_t hb = (size_t)(b * NHEAD + h) * SEQ;
    const int ntiles = (SEQ + ATK - 1) / ATK;   // 24

    {
        const int row = tid >> 1;
        const int qr = min(q0 + row, SEQ - 1);
        const __half* sp = Q + (hb + qr) * HDIM;
        #pragma unroll
        for (int c = 0; c < 4; c++) {
            const int ch = (tid & 1) * 4 + c;
            cp_async16(sbase + SWZOFF(row, ch), sp + ch * 8);
        }
    }
    const int kva = tid >> 7;
    const int kvr = (tid >> 1) & 63;
    const __half* kvsrc = kva ? V : Kp;
    const uint32_t kvdst = sbase + AT_ST0 + kva * KTILE_B;
    #define LOADKV(tt, st) do { \
        const int kr_ = min((tt) * ATK + kvr, SEQ - 1); \
        const __half* sp_ = kvsrc + (hb + kr_) * HDIM; \
        const uint32_t db_ = kvdst + (st) * AT_STAGE; \
        _Pragma("unroll") \
        for (int c_ = 0; c_ < 4; c_++) { \
            const int ch_ = (tid & 1) * 4 + c_; \
            cp_async16(db_ + SWZOFF(kvr, ch_), sp_ + ch_ * 8); \
        } \
        asm volatile("cp.async.commit_group;"); \
    } while (0)

    asm volatile("cp.async.commit_group;");
    LOADKV(0, 0);
    LOADKV(1, 1);

    float o[8][4];
    #pragma unroll
    for (int i = 0; i < 8; i++)
        #pragma unroll
        for (int j = 0; j < 4; j++) o[i][j] = 0.f;
    float l0 = 0.f, l1 = 0.f;
    uint32_t qf[4][4];
    const int tq = lane & 3;

    for (int t = 0; t < ntiles; t++) {
        if (t + 1 < ntiles) asm volatile("cp.async.wait_group 1;");
        else                asm volatile("cp.async.wait_group 0;");
        __syncthreads();

        if (t == 0) {
            #pragma unroll
            for (int ks = 0; ks < 4; ks++) {
                const int row = warp * 16 + (lane & 15);
                const uint32_t off = SWZOFF(row, ks * 2 + (lane >> 4));
                ldsm_x4(qf[ks][0], qf[ks][1], qf[ks][2], qf[ks][3], sbase + off);
            }
        }

        const uint32_t kb = sbase + AT_ST0 + (t & 1) * AT_STAGE;

        float c[8][4];
        #pragma unroll
        for (int i = 0; i < 8; i++)
            #pragma unroll
            for (int j = 0; j < 4; j++) c[i][j] = 0.f;

        #pragma unroll
        for (int ks = 0; ks < 4; ks++) {
            uint32_t bf[8][2];
            #pragma unroll
            for (int np = 0; np < 4; np++) {
                const int row = np * 16 + (lane & 7) + ((lane >> 4) & 1) * 8;
                const uint32_t off = SWZOFF(row, ks * 2 + ((lane >> 3) & 1));
                uint32_t r0, r1, r2, r3;
                ldsm_x4(r0, r1, r2, r3, kb + off);
                bf[np*2][0] = r0; bf[np*2][1] = r1; bf[np*2+1][0] = r2; bf[np*2+1][1] = r3;
            }
            #pragma unroll
            for (int nt = 0; nt < 8; nt++)
                mma_f16(c[nt], qf[ks], bf[nt]);
        }

        // ---- softmax: pack scores to fp16 pairs, ex2.approx.f16x2 ----
        const bool needmask = (t * ATK + ATK > SEQ);
        uint32_t pa[4][4];
        #pragma unroll
        for (int nt = 0; nt < 8; nt++) {
            uint32_t p01 = ex2_h2(packh2(c[nt][0], c[nt][1]));
            uint32_t p23 = ex2_h2(packh2(c[nt][2], c[nt][3]));
            if (needmask) {
                const int jc = t * ATK + nt * 8 + tq * 2;
                if (jc >= SEQ)          { p01 = 0u; p23 = 0u; }
                else if (jc + 1 >= SEQ) { p01 &= 0xFFFFu; p23 &= 0xFFFFu; }
            }
            float2 f01 = __half22float2(*reinterpret_cast<__half2*>(&p01));
            float2 f23 = __half22float2(*reinterpret_cast<__half2*>(&p23));
            l0 += f01.x + f01.y;
            l1 += f23.x + f23.y;
            pa[nt >> 1][(nt & 1) * 2 + 0] = p01;
            pa[nt >> 1][(nt & 1) * 2 + 1] = p23;
        }

        #pragma unroll
        for (int ks = 0; ks < 4; ks++) {
            uint32_t vf[8][2];
            #pragma unroll
            for (int np = 0; np < 4; np++) {
                const int row = ks * 16 + (lane & 7) + ((lane >> 3) & 1) * 8;
                const uint32_t off = SWZOFF(row, np * 2 + (lane >> 4));
                uint32_t r0, r1, r2, r3;
                ldsm_x4t(r0, r1, r2, r3, kb + KTILE_B + off);
                vf[np*2][0] = r0; vf[np*2][1] = r1; vf[np*2+1][0] = r2; vf[np*2+1][1] = r3;
            }
            #pragma unroll
            for (int nt = 0; nt < 8; nt++)
                mma_f16(o[nt], pa[ks], vf[nt]);
        }
        __syncthreads();
        if (t + 2 < ntiles) LOADKV(t + 2, t & 1);
    }

    l0 += __shfl_xor_sync(0xffffffffu, l0, 1);
    l0 += __shfl_xor_sync(0xffffffffu, l0, 2);
    l1 += __shfl_xor_sync(0xffffffffu, l1, 1);
    l1 += __shfl_xor_sync(0xffffffffu, l1, 2);
    const float inv0 = 1.0f / l0, inv1 = 1.0f / l1;
    const int token0 = q0 + warp * 16 + (lane >> 2);
    const int token1 = token0 + 8;
    #pragma unroll
    for (int nt = 0; nt < 8; nt++) {
        const int d0 = nt * 8 + tq * 2;
        if (token0 < SEQ) {
            const size_t idx = (size_t)(b * SEQ + token0) * CDIM + h * HDIM + d0;
            *reinterpret_cast<__half2*>(O + idx) =
                __floats2half2_rn(o[nt][0] * inv0, o[nt][1] * inv0);
        }
        if (token1 < SEQ) {
            const size_t idx = (size_t)(b * SEQ + token1) * CDIM + h * HDIM + d0;
            *reinterpret_cast<__half2*>(O + idx) =
                __floats2half2_rn(o[nt][2] * inv1, o[nt][3] * inv1);
        }
    }
}

// ---------------- launch ----------------
extern "C" void kernel_launch(void* const* d_in, const int* in_sizes, int n_in,
                              void* d_out, int out_size) {
    const float* x     = (const float*)d_in[0];
    const float* Wq    = (const float*)d_in[1];
    const float* bq    = (const float*)d_in[2];
    const float* Wk    = (const float*)d_in[3];
    const float* Wv    = (const float*)d_in[4];
    const float* bv    = (const float*)d_in[5];
    const float* Wo    = (const float*)d_in[6];
    const float* bo    = (const float*)d_in[7];
    const float* ln_aw = (const float*)d_in[8];
    const float* ln_ab = (const float*)d_in[9];
    const float* W1    = (const float*)d_in[10];
    const float* b1    = (const float*)d_in[11];
    const float* W2    = (const float*)d_in[12];
    const float* b2    = (const float*)d_in[13];
    const float* ln_mw = (const float*)d_in[14];
    const float* ln_mb = (const float*)d_in[15];
    const float* Wds   = (const float*)d_in[16];
    const float* bds   = (const float*)d_in[17];
    const float* Wus   = (const float*)d_in[18];
    const float* bus   = (const float*)d_in[19];
    float* out = (float*)d_out;

    float *x1, *pp;
    __half *q, *k, *v, *H, *F, *D, *W;
    cudaGetSymbolAddress((void**)&x1, g_x1);
    cudaGetSymbolAddress((void**)&pp, g_p);
    cudaGetSymbolAddress((void**)&q,  g_q);
    cudaGetSymbolAddress((void**)&k,  g_k);
    cudaGetSymbolAddress((void**)&v,  g_v);
    cudaGetSymbolAddress((void**)&H,  g_H);
    cudaGetSymbolAddress((void**)&F,  g_F);
    cudaGetSymbolAddress((void**)&D,  g_D);
    cudaGetSymbolAddress((void**)&W,  g_W);

    cudaFuncSetAttribute(gemm_mma<3, false, 128>, cudaFuncAttributeMaxDynamicSharedMemorySize, GEMM_SMEM);
    cudaFuncSetAttribute(gemm_mma<0, false, 128>, cudaFuncAttributeMaxDynamicSharedMemorySize, GEMM_SMEM);
    cudaFuncSetAttribute(gemm_mma<1, true, 128>,  cudaFuncAttributeMaxDynamicSharedMemorySize, GEMM_SMEM);
    cudaFuncSetAttribute(gemm_mma<4, false, 128>, cudaFuncAttributeMaxDynamicSharedMemorySize, GEMM_SMEM);
    cudaFuncSetAttribute(gemm_mma<1, true, 64>,   cudaFuncAttributeMaxDynamicSharedMemorySize, GEMM_SMEM);
    cudaFuncSetAttribute(gemm_mma<0, false, 64>,  cudaFuncAttributeMaxDynamicSharedMemorySize, GEMM_SMEM);
    cudaFuncSetAttribute(attn_mma, cudaFuncAttributeMaxDynamicSharedMemorySize, ATT_SMEM);

    // fused weight convert
    CvtArgs ca;
    ca.src[0] = Wq;  ca.src[1] = Wk;  ca.src[2] = Wv;  ca.src[3] = Wo;
    ca.src[4] = W1;  ca.src[5] = W2;  ca.src[6] = Wds; ca.src[7] = Wus;
    const int seg4[8] = {CC/4, CC/4, CC/4, CC/4, W1SZ/4, W1SZ/4, ASZ/4, ASZ/4};
    ca.off4[0] = 0;
    for (int i = 0; i < 8; i++) ca.off4[i + 1] = ca.off4[i] + seg4[i];
    cvt_all_kernel<<<(ca.off4[8] + 255) / 256, 256>>>(ca, W);

    const int mg = (MROWS + 127) / 128;   // 47
    const int mg64 = (MROWS + 63) / 64;   // 94
    dim3 gQKV(3 * CDIM / 128, mg);        // (24,47)
    dim3 gC(CDIM / 128, mg);              // (8,47)
    dim3 gC64(CDIM / 128, mg64);          // (8,94)
    dim3 gF(FDIM / 128, mg);              // (32,47)
    dim3 gW2(CDIM / 128, mg, 2);          // (8,47,2) split-K
    dim3 gA64(ADIM / 128, mg64);          // (2,94)
    dim3 gAt((SEQ + ATQ - 1) / ATQ, NHEAD, BATCH);

    // ---- attention ----
    ln_h_kernel<<<MROWS / 2, 256>>>(x, ln_aw, ln_ab, H);
    gemm_mma<3, false, 128><<<gQKV, 256, GEMM_SMEM>>>(H, W + OFF_WQ, bq, bv, nullptr,
        nullptr, q, k, v, MROWS, 3 * CDIM, CDIM, CDIM, QKSCALE);
    attn_mma<<<gAt, 256, ATT_SMEM>>>(q, k, v, H);
    gemm_mma<0, false, 128><<<gC, 256, GEMM_SMEM>>>(H, W + OFF_WO, bo, nullptr, x,
        x1, nullptr, nullptr, nullptr, MROWS, CDIM, CDIM, CDIM, 1.0f);

    // ---- MLP ----
    ln_h_kernel<<<MROWS / 2, 256>>>(x1, ln_mw, ln_mb, H);
    gemm_mma<1, true, 128><<<gF, 256, GEMM_SMEM>>>(H, W + OFF_W1, b1, nullptr, nullptr,
        nullptr, F, nullptr, nullptr, MROWS, FDIM, CDIM, CDIM, 1.0f);
    gemm_mma<4, false, 128><<<gW2, 256, GEMM_SMEM>>>(F, W + OFF_W2, nullptr, nullptr, nullptr,
        pp, nullptr, nullptr, nullptr, MROWS, CDIM, FDIM / 2, FDIM, 1.0f);
    red_kernel<<<(MROWS * CDIM / 4 + 255) / 256, 256>>>(pp, x1, b2, out, H);

    // ---- bottleneck adapter ----
    gemm_mma<1, true, 64><<<gA64, 256, GEMM_SMEM>>>(H, W + OFF_WDS, bds, nullptr, nullptr,
        nullptr, D, nullptr, nullptr, MROWS, ADIM, CDIM, CDIM, 1.0f);
    gemm_mma<0, false, 64><<<gC64, 256, GEMM_SMEM>>>(D, W + OFF_WUS, bus, nullptr, out,
        out, nullptr, nullptr, nullptr, MROWS, CDIM, ADIM, ADIM, 1.0f);
}

// round 17
// speedup vs baseline: 1.0081x; 1.0081x over previous
#include <cuda_runtime.h>
#include <cuda_fp16.h>
#include <math.h>
#include <stdint.h>

// ---------------- problem constants ----------------
#define BATCH   4
#define SEQ     1500
#define CDIM    1024
#define NHEAD   16
#define HDIM    64
#define FDIM    4096
#define ADIM    256
#define MROWS   (BATCH * SEQ)          // 6000
#define QKSCALE 0.35355339059327379f   // 64^-0.25
#define LOG2E   1.4426950408889634f

// ---------------- scratch ----------------
__device__ float g_x1[MROWS * CDIM];
__device__ float g_p [2 * MROWS * CDIM];   // split-K partials (W2, Wo)

__device__ __half g_q[MROWS * CDIM];
__device__ __half g_k[MROWS * CDIM];
__device__ __half g_v[MROWS * CDIM];

__device__ __half g_H[MROWS * CDIM];
__device__ __half g_F[MROWS * FDIM];
__device__ __half g_D[MROWS * ADIM];

#define CC      (CDIM * CDIM)
#define W1SZ    (FDIM * CDIM)
#define ASZ     (ADIM * CDIM)
#define OFF_WQ  0
#define OFF_WK  (CC)
#define OFF_WV  (2 * CC)
#define OFF_WO  (3 * CC)
#define OFF_W1  (4 * CC)
#define OFF_W2  (4 * CC + W1SZ)
#define OFF_WDS (4 * CC + 2 * W1SZ)
#define OFF_WUS (4 * CC + 2 * W1SZ + ASZ)
#define WTOT    (4 * CC + 2 * W1SZ + 2 * ASZ)
__device__ __half g_W[WTOT];

// ---------------- helpers ----------------
__device__ __forceinline__ float gelu_exact(float v) {
    return 0.5f * v * (1.0f + erff(v * 0.70710678118654752f));
}
__device__ __forceinline__ uint32_t smem_u32(const void* p) {
    uint32_t a;
    asm("{ .reg .u64 t; cvta.to.shared.u64 t, %1; cvt.u32.u64 %0, t; }" : "=r"(a) : "l"(p));
    return a;
}
__device__ __forceinline__ void cp_async16(uint32_t dst, const void* src) {
    asm volatile("cp.async.cg.shared.global [%0], [%1], 16;" :: "r"(dst), "l"(src));
}
__device__ __forceinline__ void ldsm_x4(uint32_t& r0, uint32_t& r1, uint32_t& r2,
                                        uint32_t& r3, uint32_t addr) {
    asm volatile("ldmatrix.sync.aligned.m8n8.x4.shared.b16 {%0,%1,%2,%3}, [%4];"
        : "=r"(r0), "=r"(r1), "=r"(r2), "=r"(r3) : "r"(addr));
}
__device__ __forceinline__ void ldsm_x4t(uint32_t& r0, uint32_t& r1, uint32_t& r2,
                                         uint32_t& r3, uint32_t addr) {
    asm volatile("ldmatrix.sync.aligned.m8n8.x4.trans.shared.b16 {%0,%1,%2,%3}, [%4];"
        : "=r"(r0), "=r"(r1), "=r"(r2), "=r"(r3) : "r"(addr));
}
__device__ __forceinline__ void mma_f16(float* c, const uint32_t* a, const uint32_t* b) {
    asm volatile("mma.sync.aligned.m16n8k16.row.col.f32.f16.f16.f32 "
        "{%0,%1,%2,%3}, {%4,%5,%6,%7}, {%8,%9}, {%0,%1,%2,%3};"
        : "+f"(c[0]), "+f"(c[1]), "+f"(c[2]), "+f"(c[3])
        : "r"(a[0]), "r"(a[1]), "r"(a[2]), "r"(a[3]), "r"(b[0]), "r"(b[1]));
}
__device__ __forceinline__ uint32_t packh2(float a, float b) {
    __half2 h = __floats2half2_rn(a, b);
    return *reinterpret_cast<uint32_t*>(&h);
}
__device__ __forceinline__ uint32_t ex2_h2(uint32_t s) {
    uint32_t p;
    asm("ex2.approx.f16x2 %0, %1;" : "=r"(p) : "r"(s));
    return p;
}
#define SWZOFF(row, ch) ((uint32_t)((((row) * 8) + ((ch) ^ ((row) & 7))) * 16))

// ---------------- fused weight conversion ----------------
struct CvtArgs {
    const float* src[8];
    int off4[9];
};
__global__ __launch_bounds__(256) void cvt_all_kernel(CvtArgs a, __half* __restrict__ W) {
    const int i = blockIdx.x * 256 + threadIdx.x;
    if (i >= a.off4[8]) return;
    int seg = 0;
    #pragma unroll
    for (int s = 1; s < 8; s++) if (i >= a.off4[s]) seg = s;
    const int li = i - a.off4[seg];
    float4 v = reinterpret_cast<const float4*>(a.src[seg])[li];
    __half2* dp = reinterpret_cast<__half2*>(W + (size_t)i * 4);
    dp[0] = __floats2half2_rn(v.x, v.y);
    dp[1] = __floats2half2_rn(v.z, v.w);
}

// ---------------- LayerNorm: 2 rows per block, 128 threads/row ----------------
__global__ __launch_bounds__(256) void ln_h_kernel(const float* __restrict__ x,
                                                   const float* __restrict__ w,
                                                   const float* __restrict__ b,
                                                   __half* __restrict__ oh) {
    __shared__ float red[2][2][4];
    const int rh  = threadIdx.x >> 7;
    const int row = blockIdx.x * 2 + rh;
    const int tid = threadIdx.x & 127;
    const int lane = threadIdx.x & 31, wid = (threadIdx.x >> 5) & 3;

    const float* xp = x + (size_t)row * CDIM;
    float4 v0 = reinterpret_cast<const float4*>(xp)[tid];
    float4 v1 = reinterpret_cast<const float4*>(xp)[tid + 128];
    float s  = v0.x + v0.y + v0.z + v0.w + v1.x + v1.y + v1.z + v1.w;
    float ss = v0.x*v0.x + v0.y*v0.y + v0.z*v0.z + v0.w*v0.w
             + v1.x*v1.x + v1.y*v1.y + v1.z*v1.z + v1.w*v1.w;
    #pragma unroll
    for (int o = 16; o; o >>= 1) {
        s  += __shfl_xor_sync(0xffffffffu, s,  o);
        ss += __shfl_xor_sync(0xffffffffu, ss, o);
    }
    if (lane == 0) { red[rh][0][wid] = s; red[rh][1][wid] = ss; }
    __syncthreads();
    float fs = 0.f, fss = 0.f;
    #pragma unroll
    for (int i = 0; i < 4; i++) { fs += red[rh][0][i]; fss += red[rh][1][i]; }
    const float mu  = fs * (1.0f / CDIM);
    const float var = fss * (1.0f / CDIM) - mu * mu;
    const float r   = rsqrtf(var + 1e-5f);

    float4 w0 = reinterpret_cast<const float4*>(w)[tid];
    float4 w1 = reinterpret_cast<const float4*>(w)[tid + 128];
    float4 b0 = reinterpret_cast<const float4*>(b)[tid];
    float4 b1 = reinterpret_cast<const float4*>(b)[tid + 128];
    __half2* hp = reinterpret_cast<__half2*>(oh + (size_t)row * CDIM);
    hp[tid * 2 + 0] = __floats2half2_rn((v0.x - mu) * r * w0.x + b0.x,
                                        (v0.y - mu) * r * w0.y + b0.y);
    hp[tid * 2 + 1] = __floats2half2_rn((v0.z - mu) * r * w0.z + b0.z,
                                        (v0.w - mu) * r * w0.w + b0.w);
    hp[256 + tid * 2 + 0] = __floats2half2_rn((v1.x - mu) * r * w1.x + b1.x,
                                              (v1.y - mu) * r * w1.y + b1.y);
    hp[256 + tid * 2 + 1] = __floats2half2_rn((v1.z - mu) * r * w1.z + b1.z,
                                              (v1.w - mu) * r * w1.w + b1.w);
}

// ---------------- split-K reduction: out = p0 + p1 + bias + res; optional H = half(out) ----------------
template<bool WRH>
__global__ __launch_bounds__(256) void red_kernel(const float* __restrict__ p,
                                                  const float* __restrict__ res,
                                                  const float* __restrict__ bias,
                                                  float* __restrict__ out,
                                                  __half* __restrict__ H) {
    const int i = blockIdx.x * 256 + threadIdx.x;      // float4 units
    if (i >= MROWS * CDIM / 4) return;
    float4 a = reinterpret_cast<const float4*>(p)[i];
    float4 b = reinterpret_cast<const float4*>(p)[i + MROWS * CDIM / 4];
    float4 r = reinterpret_cast<const float4*>(res)[i];
    float4 bb = reinterpret_cast<const float4*>(bias)[i & 255];
    float4 o;
    o.x = a.x + b.x + r.x + bb.x;
    o.y = a.y + b.y + r.y + bb.y;
    o.z = a.z + b.z + r.z + bb.z;
    o.w = a.w + b.w + r.w + bb.w;
    reinterpret_cast<float4*>(out)[i] = o;
    if (WRH) {
        __half2* hp = reinterpret_cast<__half2*>(H + (size_t)i * 4);
        hp[0] = __floats2half2_rn(o.x, o.y);
        hp[1] = __floats2half2_rn(o.z, o.w);
    }
}

// ---------------- fp16 tensor-core GEMM, multi-stage cp.async pipeline (R13 mainloop) ----------------
// MODE 0: v = acc+bias(+res) -> fp32 out (optional half copy to Oh)
// MODE 1: v = gelu(acc+bias) -> half out (Oh)
// MODE 3: fused QKV; MODE 4: split-K partial
#define GEMM_SMEM 98304

template<int MODE, bool HCOPY, int TM>
__global__ __launch_bounds__(256, 2) void gemm_mma(
        const __half* __restrict__ A, const __half* __restrict__ B,
        const float* __restrict__ bias, const float* __restrict__ bias2,
        const float* __restrict__ res,
        float* __restrict__ out, __half* __restrict__ Oh,
        __half* __restrict__ Kp, __half* __restrict__ Vp,
        int M, int N, int K, int ld, float scale) {
    constexpr int WM = TM / 32;
    constexpr int WN = 8 / WM;
    constexpr int WNC = 128 / WN;
    constexpr int NT = WNC / 8;
    constexpr int TILEA = TM * 128;
    constexpr int TILEB2 = 128 * 128;
    constexpr int STAGE = TILEA + TILEB2;
    constexpr int NST = (TM == 128) ? 3 : 4;
    constexpr int P = NST - 1;

    extern __shared__ char smem[];
    const uint32_t sbase = smem_u32(smem);
    const int tid  = threadIdx.x;
    const int warp = tid >> 5, lane = tid & 31;
    const int bm = blockIdx.y * TM, bn = blockIdx.x * 128;
    const int wm = warp % WM, wn = warp / WM;

    const bool lact = tid < TM + 128;
    const bool isA = tid < TM;
    const int lrow = isA ? tid : tid - TM;
    const __half* lsrc = isA ? A : B;
    const int gr = isA ? min(bm + lrow, M - 1) : (bn + lrow);
    const int koff = (MODE == 4) ? blockIdx.z * K : 0;
    const __half* src = lsrc + (size_t)gr * ld + koff;
    const uint32_t dbase0 = sbase + (isA ? 0 : TILEA);
    uint32_t doff[8];
    #pragma unroll
    for (int c = 0; c < 8; c++) doff[c] = SWZOFF(lrow, c);

    float acc[2][NT][4];
    #pragma unroll
    for (int a = 0; a < 2; a++)
        #pragma unroll
        for (int b = 0; b < NT; b++)
            #pragma unroll
            for (int c = 0; c < 4; c++) acc[a][b][c] = 0.f;

    const int nch = K / 64;

    #pragma unroll
    for (int p = 0; p < P; p++) {
        if (p < nch && lact) {
            const uint32_t db = dbase0 + p * STAGE;
            const int k0 = p * 64;
            #pragma unroll
            for (int c = 0; c < 8; c++) cp_async16(db + doff[c], src + k0 + c * 8);
        }
        asm volatile("cp.async.commit_group;");
    }

    const int arow = (lane & 15);
    const int acsel = lane >> 4;
    const int brow = (lane & 7) + ((lane >> 4) & 1) * 8;
    const int bcsel = (lane >> 3) & 1;

    int stc = 0;
    for (int kc = 0; kc < nch; kc++) {
        if constexpr (NST == 3) asm volatile("cp.async.wait_group 1;");
        else                    asm volatile("cp.async.wait_group 2;");
        __syncthreads();

        const uint32_t base = sbase + stc * STAGE;
        const uint32_t aB = base, bB = base + TILEA;

        // ---- peel ks=0 fragment loads before issuing next chunk's cp.async ----
        uint32_t af0[2][4], bf0[NT][2];
        #pragma unroll
        for (int mt = 0; mt < 2; mt++) {
            const int row = wm * 32 + mt * 16 + arow;
            const uint32_t off = SWZOFF(row, acsel);
            ldsm_x4(af0[mt][0], af0[mt][1], af0[mt][2], af0[mt][3], aB + off);
        }
        #pragma unroll
        for (int np = 0; np < NT / 2; np++) {
            const int row = wn * WNC + np * 16 + brow;
            const uint32_t off = SWZOFF(row, bcsel);
            uint32_t r0, r1, r2, r3;
            ldsm_x4(r0, r1, r2, r3, bB + off);
            bf0[np*2][0] = r0; bf0[np*2][1] = r1; bf0[np*2+1][0] = r2; bf0[np*2+1][1] = r3;
        }

        // ---- issue next chunk load (overlaps ldmatrix latency) ----
        {
            const int cload = kc + P;
            if (cload < nch && lact) {
                const int sti = (stc == 0) ? (NST - 1) : (stc - 1);
                const uint32_t db = dbase0 + sti * STAGE;
                const int k0 = cload * 64;
                #pragma unroll
                for (int c = 0; c < 8; c++) cp_async16(db + doff[c], src + k0 + c * 8);
            }
            asm volatile("cp.async.commit_group;");
        }

        // ---- ks=0 mma ----
        #pragma unroll
        for (int mt = 0; mt < 2; mt++)
            #pragma unroll
            for (int nt = 0; nt < NT; nt++)
                mma_f16(acc[mt][nt], af0[mt], bf0[nt]);

        // ---- ks = 1..3 ----
        #pragma unroll
        for (int ks = 1; ks < 4; ks++) {
            uint32_t af[2][4], bf[NT][2];
            #pragma unroll
            for (int mt = 0; mt < 2; mt++) {
                const int row = wm * 32 + mt * 16 + arow;
                const uint32_t off = SWZOFF(row, ks * 2 + acsel);
                ldsm_x4(af[mt][0], af[mt][1], af[mt][2], af[mt][3], aB + off);
            }
            #pragma unroll
            for (int np = 0; np < NT / 2; np++) {
                const int row = wn * WNC + np * 16 + brow;
                const uint32_t off = SWZOFF(row, ks * 2 + bcsel);
                uint32_t r0, r1, r2, r3;
                ldsm_x4(r0, r1, r2, r3, bB + off);
                bf[np*2][0] = r0; bf[np*2][1] = r1; bf[np*2+1][0] = r2; bf[np*2+1][1] = r3;
            }
            #pragma unroll
            for (int mt = 0; mt < 2; mt++)
                #pragma unroll
                for (int nt = 0; nt < NT; nt++)
                    mma_f16(acc[mt][nt], af[mt], bf[nt]);
        }
        stc = (stc + 1 == NST) ? 0 : stc + 1;
    }

    // ---------------- epilogue ----------------
    __half* dst3 = Oh;
    const float* bb3 = bias;
    float sc3 = scale;
    if (MODE == 3) {
        const int seg = bn >> 10;
        dst3 = (seg == 0) ? Oh : ((seg == 1) ? Kp : Vp);
        bb3  = (seg == 0) ? bias : ((seg == 2) ? bias2 : nullptr);
        sc3  = (seg == 0) ? scale * LOG2E : ((seg == 1) ? scale : 1.0f);
    }
    float* out4 = out;
    if (MODE == 4) out4 = out + (size_t)blockIdx.z * M * N;

    const int g = lane >> 2, t = lane & 3;
    #pragma unroll
    for (int mt = 0; mt < 2; mt++) {
        #pragma unroll
        for (int half = 0; half < 2; half++) {
            const int m = bm + wm * 32 + mt * 16 + g + half * 8;
            if (m >= M) continue;
            int bI = 0, sI = 0;
            if (MODE == 3) { bI = m / SEQ; sI = m - bI * SEQ; }
            #pragma unroll
            for (int nt = 0; nt < NT; nt++) {
                const int n = bn + wn * WNC + nt * 8 + t * 2;
                float v0 = acc[mt][nt][half * 2 + 0];
                float v1 = acc[mt][nt][half * 2 + 1];
                if (MODE == 4) {
                    const size_t idx = (size_t)m * N + n;
                    *reinterpret_cast<float2*>(out4 + idx) = make_float2(v0, v1);
                } else if (MODE == 3) {
                    const int nn = n & 1023;
                    if (bb3) {
                        float2 b2 = *reinterpret_cast<const float2*>(bb3 + nn);
                        v0 += b2.x; v1 += b2.y;
                    }
                    v0 *= sc3; v1 *= sc3;
                    const int hd = nn >> 6, dd = nn & 63;
                    const size_t idx = (((size_t)bI * NHEAD + hd) * SEQ + sI) * HDIM + dd;
                    *reinterpret_cast<__half2*>(dst3 + idx) = __floats2half2_rn(v0, v1);
                } else {
                    if (bias) {
                        float2 b2 = *reinterpret_cast<const float2*>(bias + n);
                        v0 += b2.x; v1 += b2.y;
                    }
                    if (MODE == 1) {
                        v0 = gelu_exact(v0); v1 = gelu_exact(v1);
                        const size_t idx = (size_t)m * N + n;
                        *reinterpret_cast<__half2*>(Oh + idx) = __floats2half2_rn(v0, v1);
                    } else {
                        const size_t idx = (size_t)m * N + n;
                        if (res) {
                            float2 r2 = *reinterpret_cast<const float2*>(res + idx);
                            v0 += r2.x; v1 += r2.y;
                        }
                        *reinterpret_cast<float2*>(out + idx) = make_float2(v0, v1);
                        if (HCOPY)
                            *reinterpret_cast<__half2*>(Oh + idx) = __floats2half2_rn(v0, v1);
                    }
                }
            }
        }
    }
}

// ---------------- tensor-core flash attention (fp16, static-max softmax, f16x2 ex2) ----------------
// R13 configuration: 64-row KV tiles, 2-stage double buffer (measured optimum).
#define ATQ 128
#define ATK 64
#define QTILE_B (ATQ * 128)
#define KTILE_B (ATK * 128)
#define AT_ST0  (QTILE_B)
#define AT_STAGE (2 * KTILE_B)
#define ATT_SMEM (QTILE_B + 2 * AT_STAGE)   // 49152

__global__ __launch_bounds__(256, 2) void attn_mma(
        const __half* __restrict__ Q, const __half* __restrict__ Kp,
        const __half* __restrict__ V, __half* __restrict__ O) {
    extern __shared__ char smem[];
    const uint32_t sbase = smem_u32(smem);
    const int tid = threadIdx.x;
    const int warp = tid >> 5, lane = tid & 31;
    const int b = blockIdx.z, h = blockIdx.y;
    const int q0 = blockIdx.x * ATQ;
    const size_t hb = (size_t)(b * NHEAD + h) * SEQ;
    const int ntiles = (SEQ + ATK - 1) / ATK;   // 24

    {
        const int row = tid >> 1;
        const int qr = min(q0 + row, SEQ - 1);
        const __half* sp = Q + (hb + qr) * HDIM;
        #pragma unroll
        for (int c = 0; c < 4; c++) {
            const int ch = (tid & 1) * 4 + c;
            cp_async16(sbase + SWZOFF(row, ch), sp + ch * 8);
        }
    }
    const int kva = tid >> 7;
    const int kvr = (tid >> 1) & 63;
    const __half* kvsrc = kva ? V : Kp;
    const uint32_t kvdst = sbase + AT_ST0 + kva * KTILE_B;
    #define LOADKV(tt, st) do { \
        const int kr_ = min((tt) * ATK + kvr, SEQ - 1); \
        const __half* sp_ = kvsrc + (hb + kr_) * HDIM; \
        const uint32_t db_ = kvdst + (st) * AT_STAGE; \
        _Pragma("unroll") \
        for (int c_ = 0; c_ < 4; c_++) { \
            const int ch_ = (tid & 1) * 4 + c_; \
            cp_async16(db_ + SWZOFF(kvr, ch_), sp_ + ch_ * 8); \
        } \
        asm volatile("cp.async.commit_group;"); \
    } while (0)

    asm volatile("cp.async.commit_group;");
    LOADKV(0, 0);
    LOADKV(1, 1);

    float o[8][4];
    #pragma unroll
    for (int i = 0; i < 8; i++)
        #pragma unroll
        for (int j = 0; j < 4; j++) o[i][j] = 0.f;
    float l0 = 0.f, l1 = 0.f;
    uint32_t qf[4][4];
    const int tq = lane & 3;

    for (int t = 0; t < ntiles; t++) {
        if (t + 1 < ntiles) asm volatile("cp.async.wait_group 1;");
        else                asm volatile("cp.async.wait_group 0;");
        __syncthreads();

        if (t == 0) {
            #pragma unroll
            for (int ks = 0; ks < 4; ks++) {
                const int row = warp * 16 + (lane & 15);
                const uint32_t off = SWZOFF(row, ks * 2 + (lane >> 4));
                ldsm_x4(qf[ks][0], qf[ks][1], qf[ks][2], qf[ks][3], sbase + off);
            }
        }

        const uint32_t kb = sbase + AT_ST0 + (t & 1) * AT_STAGE;

        float c[8][4];
        #pragma unroll
        for (int i = 0; i < 8; i++)
            #pragma unroll
            for (int j = 0; j < 4; j++) c[i][j] = 0.f;

        #pragma unroll
        for (int ks = 0; ks < 4; ks++) {
            uint32_t bf[8][2];
            #pragma unroll
            for (int np = 0; np < 4; np++) {
                const int row = np * 16 + (lane & 7) + ((lane >> 4) & 1) * 8;
                const uint32_t off = SWZOFF(row, ks * 2 + ((lane >> 3) & 1));
                uint32_t r0, r1, r2, r3;
                ldsm_x4(r0, r1, r2, r3, kb + off);
                bf[np*2][0] = r0; bf[np*2][1] = r1; bf[np*2+1][0] = r2; bf[np*2+1][1] = r3;
            }
            #pragma unroll
            for (int nt = 0; nt < 8; nt++)
                mma_f16(c[nt], qf[ks], bf[nt]);
        }

        // ---- softmax: pack scores to fp16 pairs, ex2.approx.f16x2 ----
        const bool needmask = (t * ATK + ATK > SEQ);
        uint32_t pa[4][4];
        #pragma unroll
        for (int nt = 0; nt < 8; nt++) {
            uint32_t p01 = ex2_h2(packh2(c[nt][0], c[nt][1]));
            uint32_t p23 = ex2_h2(packh2(c[nt][2], c[nt][3]));
            if (needmask) {
                const int jc = t * ATK + nt * 8 + tq * 2;
                if (jc >= SEQ)          { p01 = 0u; p23 = 0u; }
                else if (jc + 1 >= SEQ) { p01 &= 0xFFFFu; p23 &= 0xFFFFu; }
            }
            float2 f01 = __half22float2(*reinterpret_cast<__half2*>(&p01));
            float2 f23 = __half22float2(*reinterpret_cast<__half2*>(&p23));
            l0 += f01.x + f01.y;
            l1 += f23.x + f23.y;
            pa[nt >> 1][(nt & 1) * 2 + 0] = p01;
            pa[nt >> 1][(nt & 1) * 2 + 1] = p23;
        }

        #pragma unroll
        for (int ks = 0; ks < 4; ks++) {
            uint32_t vf[8][2];
            #pragma unroll
            for (int np = 0; np < 4; np++) {
                const int row = ks * 16 + (lane & 7) + ((lane >> 3) & 1) * 8;
                const uint32_t off = SWZOFF(row, np * 2 + (lane >> 4));
                uint32_t r0, r1, r2, r3;
                ldsm_x4t(r0, r1, r2, r3, kb + KTILE_B + off);
                vf[np*2][0] = r0; vf[np*2][1] = r1; vf[np*2+1][0] = r2; vf[np*2+1][1] = r3;
            }
            #pragma unroll
            for (int nt = 0; nt < 8; nt++)
                mma_f16(o[nt], pa[ks], vf[nt]);
        }
        __syncthreads();
        if (t + 2 < ntiles) LOADKV(t + 2, t & 1);
    }

    l0 += __shfl_xor_sync(0xffffffffu, l0, 1);
    l0 += __shfl_xor_sync(0xffffffffu, l0, 2);
    l1 += __shfl_xor_sync(0xffffffffu, l1, 1);
    l1 += __shfl_xor_sync(0xffffffffu, l1, 2);
    const float inv0 = 1.0f / l0, inv1 = 1.0f / l1;
    const int token0 = q0 + warp * 16 + (lane >> 2);
    const int token1 = token0 + 8;
    #pragma unroll
    for (int nt = 0; nt < 8; nt++) {
        const int d0 = nt * 8 + tq * 2;
        if (token0 < SEQ) {
            const size_t idx = (size_t)(b * SEQ + token0) * CDIM + h * HDIM + d0;
            *reinterpret_cast<__half2*>(O + idx) =
                __floats2half2_rn(o[nt][0] * inv0, o[nt][1] * inv0);
        }
        if (token1 < SEQ) {
            const size_t idx = (size_t)(b * SEQ + token1) * CDIM + h * HDIM + d0;
            *reinterpret_cast<__half2*>(O + idx) =
                __floats2half2_rn(o[nt][2] * inv1, o[nt][3] * inv1);
        }
    }
}

// ---------------- launch ----------------
extern "C" void kernel_launch(void* const* d_in, const int* in_sizes, int n_in,
                              void* d_out, int out_size) {
    const float* x     = (const float*)d_in[0];
    const float* Wq    = (const float*)d_in[1];
    const float* bq    = (const float*)d_in[2];
    const float* Wk    = (const float*)d_in[3];
    const float* Wv    = (const float*)d_in[4];
    const float* bv    = (const float*)d_in[5];
    const float* Wo    = (const float*)d_in[6];
    const float* bo    = (const float*)d_in[7];
    const float* ln_aw = (const float*)d_in[8];
    const float* ln_ab = (const float*)d_in[9];
    const float* W1    = (const float*)d_in[10];
    const float* b1    = (const float*)d_in[11];
    const float* W2    = (const float*)d_in[12];
    const float* b2    = (const float*)d_in[13];
    const float* ln_mw = (const float*)d_in[14];
    const float* ln_mb = (const float*)d_in[15];
    const float* Wds   = (const float*)d_in[16];
    const float* bds   = (const float*)d_in[17];
    const float* Wus   = (const float*)d_in[18];
    const float* bus   = (const float*)d_in[19];
    float* out = (float*)d_out;

    float *x1, *pp;
    __half *q, *k, *v, *H, *F, *D, *W;
    cudaGetSymbolAddress((void**)&x1, g_x1);
    cudaGetSymbolAddress((void**)&pp, g_p);
    cudaGetSymbolAddress((void**)&q,  g_q);
    cudaGetSymbolAddress((void**)&k,  g_k);
    cudaGetSymbolAddress((void**)&v,  g_v);
    cudaGetSymbolAddress((void**)&H,  g_H);
    cudaGetSymbolAddress((void**)&F,  g_F);
    cudaGetSymbolAddress((void**)&D,  g_D);
    cudaGetSymbolAddress((void**)&W,  g_W);

    cudaFuncSetAttribute(gemm_mma<3, false, 128>, cudaFuncAttributeMaxDynamicSharedMemorySize, GEMM_SMEM);
    cudaFuncSetAttribute(gemm_mma<0, false, 128>, cudaFuncAttributeMaxDynamicSharedMemorySize, GEMM_SMEM);
    cudaFuncSetAttribute(gemm_mma<1, true, 128>,  cudaFuncAttributeMaxDynamicSharedMemorySize, GEMM_SMEM);
    cudaFuncSetAttribute(gemm_mma<4, false, 128>, cudaFuncAttributeMaxDynamicSharedMemorySize, GEMM_SMEM);
    cudaFuncSetAttribute(gemm_mma<1, true, 64>,   cudaFuncAttributeMaxDynamicSharedMemorySize, GEMM_SMEM);
    cudaFuncSetAttribute(attn_mma, cudaFuncAttributeMaxDynamicSharedMemorySize, ATT_SMEM);

    // fused weight convert
    CvtArgs ca;
    ca.src[0] = Wq;  ca.src[1] = Wk;  ca.src[2] = Wv;  ca.src[3] = Wo;
    ca.src[4] = W1;  ca.src[5] = W2;  ca.src[6] = Wds; ca.src[7] = Wus;
    const int seg4[8] = {CC/4, CC/4, CC/4, CC/4, W1SZ/4, W1SZ/4, ASZ/4, ASZ/4};
    ca.off4[0] = 0;
    for (int i = 0; i < 8; i++) ca.off4[i + 1] = ca.off4[i] + seg4[i];
    cvt_all_kernel<<<(ca.off4[8] + 255) / 256, 256>>>(ca, W);

    const int mg = (MROWS + 127) / 128;   // 47
    const int mg64 = (MROWS + 63) / 64;   // 94
    dim3 gQKV(3 * CDIM / 128, mg);        // (24,47)
    dim3 gC(CDIM / 128, mg);              // (8,47)
    dim3 gF(FDIM / 128, mg);              // (32,47)
    dim3 gSK(CDIM / 128, mg, 2);          // (8,47,2) split-K
    dim3 gA64(ADIM / 128, mg64);          // (2,94)
    dim3 gAt((SEQ + ATQ - 1) / ATQ, NHEAD, BATCH);
    const int nred = (MROWS * CDIM / 4 + 255) / 256;

    // ---- attention ----
    ln_h_kernel<<<MROWS / 2, 256>>>(x, ln_aw, ln_ab, H);
    gemm_mma<3, false, 128><<<gQKV, 256, GEMM_SMEM>>>(H, W + OFF_WQ, bq, bv, nullptr,
        nullptr, q, k, v, MROWS, 3 * CDIM, CDIM, CDIM, QKSCALE);
    attn_mma<<<gAt, 256, ATT_SMEM>>>(q, k, v, H);
    // Wo: split-K=2 -> partials, reduction fuses bias + residual(x) -> x1 (fp32 only)
    gemm_mma<4, false, 128><<<gSK, 256, GEMM_SMEM>>>(H, W + OFF_WO, nullptr, nullptr, nullptr,
        pp, nullptr, nullptr, nullptr, MROWS, CDIM, CDIM / 2, CDIM, 1.0f);
    red_kernel<false><<<nred, 256>>>(pp, x, bo, x1, nullptr);

    // ---- MLP ----
    ln_h_kernel<<<MROWS / 2, 256>>>(x1, ln_mw, ln_mb, H);
    gemm_mma<1, true, 128><<<gF, 256, GEMM_SMEM>>>(H, W + OFF_W1, b1, nullptr, nullptr,
        nullptr, F, nullptr, nullptr, MROWS, FDIM, CDIM, CDIM, 1.0f);
    gemm_mma<4, false, 128><<<gSK, 256, GEMM_SMEM>>>(F, W + OFF_W2, nullptr, nullptr, nullptr,
        pp, nullptr, nullptr, nullptr, MROWS, CDIM, FDIM / 2, FDIM, 1.0f);
    red_kernel<true><<<nred, 256>>>(pp, x1, b2, out, H);

    // ---- bottleneck adapter ----
    gemm_mma<1, true, 64><<<gA64, 256, GEMM_SMEM>>>(H, W + OFF_WDS, bds, nullptr, nullptr,
        nullptr, D, nullptr, nullptr, MROWS, ADIM, CDIM, CDIM, 1.0f);
    gemm_mma<0, false, 128><<<gC, 256, GEMM_SMEM>>>(D, W + OFF_WUS, bus, nullptr, out,
        out, nullptr, nullptr, nullptr, MROWS, CDIM, ADIM, ADIM, 1.0f);
}